// round 1
// baseline (speedup 1.0000x reference)
#include <cuda_runtime.h>
#include <cstdint>

#define Nn 64
#define Bb 256
#define Cc 256
#define Hh 4
#define HDd 64
#define Tt 8
#define Mm 128
#define Rr (Nn*Bb)   // 16384 rows

// ---------------- scratch (no allocations allowed) ----------------
__device__ float g_msgs[(size_t)Bb*Nn*Cc];   // [B,N,C] pre-out_w messages
__device__ float g_bq  [(size_t)Rr*Cc];      // [N*B, C]
__device__ float g_bqk [(size_t)Rr*Cc];      // [N*B, C]  = bq @ bk_w^T
__device__ float g_wbuf[(size_t)Rr*Cc];      // [N*B, C]  weighted buffer sum
__device__ float g_s   [(size_t)Rr];         // [N*B]     sum of weights

// ---------------- fused graph attention per (b,h) ----------------
// grid = B*H blocks, 256 threads. dyn smem = 3 * 64*68 floats.
__global__ void attn_kernel(const float* __restrict__ q, const float* __restrict__ k,
                            const float* __restrict__ v, const float* __restrict__ sg,
                            const float* __restrict__ ctrl, const float* __restrict__ bond,
                            float* __restrict__ msgs, float* __restrict__ attn_out) {
    extern __shared__ float sm[];
    float* Qs = sm;               // 64 x 68
    float* Ks = sm + 64*68;       // 64 x 68  (reused as Vs)
    float* Ls = sm + 2*64*68;     // 64 x 68  (logits -> attn)

    const int bid = blockIdx.x;
    const int b = bid >> 2;       // H = 4
    const int hh = bid & 3;
    const int tid = threadIdx.x;

    // load Q,K tiles (row = node n, 64 floats from head slice)
    #pragma unroll
    for (int i = 0; i < 4; i++) {
        int t = tid + i * 256;          // 0..1023 float4 tasks
        int row = t >> 4;
        int col = (t & 15) * 4;
        size_t g = ((size_t)row * Bb + b) * Cc + hh * HDd + col;
        *(float4*)&Qs[row*68 + col] = *(const float4*)&q[g];
        *(float4*)&Ks[row*68 + col] = *(const float4*)&k[g];
    }
    __syncthreads();

    const int n  = tid >> 2;
    const int m0 = (tid & 3) * 16;
    float lg[16];
    #pragma unroll
    for (int j = 0; j < 16; j++) lg[j] = 0.f;
    for (int d = 0; d < 64; d++) {
        float qv = Qs[n*68 + d];
        #pragma unroll
        for (int j = 0; j < 16; j++) lg[j] += qv * Ks[(m0+j)*68 + d];
    }
    #pragma unroll
    for (int j = 0; j < 16; j++) {
        int m = m0 + j;
        float val = lg[j] * 0.125f + bond[n*Nn + m] + ctrl[((size_t)m*Bb + b)*Hh + hh];
        if (m == n) val = -1e30f;       // mask self
        Ls[n*68 + m] = val;
    }
    __syncthreads();

    // overwrite Ks with gated V (logits already consumed K)
    #pragma unroll
    for (int i = 0; i < 4; i++) {
        int t = tid + i * 256;
        int row = t >> 4;
        int col = (t & 15) * 4;
        size_t g = ((size_t)row * Bb + b) * Cc + hh * HDd + col;
        float4 vv = *(const float4*)&v[g];
        float4 gg = *(const float4*)&sg[g];
        vv.x *= gg.x; vv.y *= gg.y; vv.z *= gg.z; vv.w *= gg.w;
        *(float4*)&Ks[row*68 + col] = vv;
    }

    // exact top-8 (selection by index, matches jax tie-breaking) + softmax
    if (tid < 64) {
        int row = tid;
        unsigned long long sel = 0ull;
        float rowmax = -1e30f;
        for (int it = 0; it < 8; it++) {
            float best = -3e38f; int bi = 0;
            for (int m = 0; m < 64; m++) {
                float val = Ls[row*68 + m];
                if (!((sel >> m) & 1ull) && val > best) { best = val; bi = m; }
            }
            sel |= 1ull << bi;
            if (it == 0) rowmax = best;
        }
        float ssum = 0.f;
        for (int m = 0; m < 64; m++)
            if ((sel >> m) & 1ull) ssum += __expf(Ls[row*68 + m] - rowmax);
        float inv = 1.f / ssum;
        size_t ao = (((size_t)b * Hh + hh) * Nn + row) * Nn;
        for (int m = 0; m < 64; m++) {
            float a = ((sel >> m) & 1ull) ? __expf(Ls[row*68 + m] - rowmax) * inv : 0.f;
            attn_out[ao + m] = a;
            Ls[row*68 + m] = a;
        }
    }
    __syncthreads();

    // msgs = attn @ Vg   (thread: row n, 16 d's)
    float acc[16];
    #pragma unroll
    for (int j = 0; j < 16; j++) acc[j] = 0.f;
    const int d0 = (tid & 3) * 16;
    for (int m = 0; m < 64; m++) {
        float a = Ls[n*68 + m];
        #pragma unroll
        for (int j = 0; j < 16; j++) acc[j] += a * Ks[m*68 + d0 + j];
    }
    size_t o = ((size_t)b * Nn + n) * Cc + hh * HDd + d0;
    #pragma unroll
    for (int j = 0; j < 16; j++) msgs[o + j] = acc[j];
}

// ---------------- buffer shift: new_buf[:,:,0:7,:] = buffers[:,:,1:8,:] ----------------
__global__ void shift_copy(const float4* __restrict__ src, float4* __restrict__ dst) {
    const long total = (long)Rr * 7 * 64;     // float4 count
    for (long i = (long)blockIdx.x * blockDim.x + threadIdx.x; i < total;
         i += (long)gridDim.x * blockDim.x) {
        long c4 = i & 63;
        long t  = (i >> 6) % 7;
        long r  = i / (7 * 64);
        dst[(r * 8 + t) * 64 + c4] = src[(r * 8 + t + 1) * 64 + c4];
    }
}

// ---------------- generic 128x128-tile SGEMM with epilogue ----------------
struct EpiMsgs {   // out_w GEMM: bias + recv gate, write into new_buf slot T-1
    const float* out_b; const float* recv; float* nb;
    __device__ __forceinline__ void store(int r, int c, float acc) const {
        int n = r & 63, b = r >> 6;                       // r = b*N + n
        size_t rb = (size_t)n * Bb + b;
        float val = (acc + out_b[c]) * recv[rb * Cc + c];
        nb[(rb * Tt + (Tt - 1)) * Cc + c] = val;
    }
};
struct EpiBias {
    float* out; const float* bias;
    __device__ __forceinline__ void store(int r, int c, float acc) const {
        out[(size_t)r * Cc + c] = acc + bias[c];
    }
};
struct EpiPlain {
    float* out;
    __device__ __forceinline__ void store(int r, int c, float acc) const {
        out[(size_t)r * Cc + c] = acc;
    }
};
struct EpiRead {
    float* out; const float* bias; const float* s;
    __device__ __forceinline__ void store(int r, int c, float acc) const {
        out[(size_t)r * Cc + c] = acc + s[r] * bias[c];
    }
};

template<bool TRANSB, typename Epi>
__global__ void __launch_bounds__(256, 2)
gemm128(const float* __restrict__ A, const float* __restrict__ Bw, int K, Epi epi) {
    __shared__ float As[16][128];
    __shared__ float Bs[16][128];
    const int tid = threadIdx.x;
    const int tx = tid & 15, ty = tid >> 4;
    const int r0 = blockIdx.x * 128, c0 = blockIdx.y * 128;

    float acc[8][8];
    #pragma unroll
    for (int i = 0; i < 8; i++)
        #pragma unroll
        for (int j = 0; j < 8; j++) acc[i][j] = 0.f;

    for (int k0 = 0; k0 < K; k0 += 16) {
        #pragma unroll
        for (int i = 0; i < 2; i++) {
            int t = tid * 2 + i;                 // 512 float4 tasks
            int ar = t >> 2;                     // 0..127
            int ak = (t & 3) * 4;
            float4 vA = *(const float4*)&A[(size_t)(r0 + ar) * K + k0 + ak];
            As[ak+0][ar] = vA.x; As[ak+1][ar] = vA.y;
            As[ak+2][ar] = vA.z; As[ak+3][ar] = vA.w;
        }
        if (!TRANSB) {
            #pragma unroll
            for (int i = 0; i < 2; i++) {
                int t = tid * 2 + i;
                int bk = t >> 5; int bc = (t & 31) * 4;
                *(float4*)&Bs[bk][bc] = *(const float4*)&Bw[(size_t)(k0 + bk) * Cc + c0 + bc];
            }
        } else {
            #pragma unroll
            for (int i = 0; i < 2; i++) {
                int t = tid * 2 + i;
                int bc = t >> 2; int bk = (t & 3) * 4;
                float4 vB = *(const float4*)&Bw[(size_t)(c0 + bc) * K + k0 + bk];
                Bs[bk+0][bc] = vB.x; Bs[bk+1][bc] = vB.y;
                Bs[bk+2][bc] = vB.z; Bs[bk+3][bc] = vB.w;
            }
        }
        __syncthreads();
        #pragma unroll
        for (int kk = 0; kk < 16; kk++) {
            float a[8], bb[8];
            *(float4*)&a[0]  = *(float4*)&As[kk][ty*8];
            *(float4*)&a[4]  = *(float4*)&As[kk][ty*8 + 4];
            *(float4*)&bb[0] = *(float4*)&Bs[kk][tx*8];
            *(float4*)&bb[4] = *(float4*)&Bs[kk][tx*8 + 4];
            #pragma unroll
            for (int i = 0; i < 8; i++)
                #pragma unroll
                for (int j = 0; j < 8; j++) acc[i][j] += a[i] * bb[j];
        }
        __syncthreads();
    }
    #pragma unroll
    for (int i = 0; i < 8; i++)
        #pragma unroll
        for (int j = 0; j < 8; j++)
            epi.store(r0 + ty*8 + i, c0 + tx*8 + j, acc[i][j]);
}

// ---------------- temporal: ba softmax + weighted buffer sum ----------------
__global__ void temporal_kernel(const float* __restrict__ bqk,
                                const float* __restrict__ bq,
                                const float* __restrict__ bk_b,
                                const float* __restrict__ newbuf,
                                const float* __restrict__ decay_logit,
                                float* __restrict__ wbuf,
                                float* __restrict__ svec) {
    const int r = blockIdx.x;            // r = n*B + b
    const int c = threadIdx.x;           // 0..255
    const float* nb = newbuf + (size_t)r * (Tt * Cc);

    float qk = bqk[(size_t)r * Cc + c];
    float p[9];
    #pragma unroll
    for (int t = 0; t < 8; t++) p[t] = qk * nb[t * Cc + c];
    p[8] = bq[(size_t)r * Cc + c] * bk_b[c];

    #pragma unroll
    for (int t = 0; t < 9; t++)
        #pragma unroll
        for (int o = 16; o > 0; o >>= 1)
            p[t] += __shfl_xor_sync(0xffffffffu, p[t], o);

    __shared__ float red[8][9];
    __shared__ float wsh[8];
    __shared__ float ssh;
    int warp = c >> 5, lane = c & 31;
    if (lane == 0) {
        #pragma unroll
        for (int t = 0; t < 9; t++) red[warp][t] = p[t];
    }
    __syncthreads();
    if (c == 0) {
        float bqb = 0.f;
        #pragma unroll
        for (int w = 0; w < 8; w++) bqb += red[w][8];
        float ba[8]; float mx = -3e38f;
        #pragma unroll
        for (int t = 0; t < 8; t++) {
            float s = 0.f;
            #pragma unroll
            for (int w = 0; w < 8; w++) s += red[w][t];
            ba[t] = (s + bqb) * 0.0625f;          // / sqrt(256)
            mx = fmaxf(mx, ba[t]);
        }
        float sum = 0.f;
        #pragma unroll
        for (int t = 0; t < 8; t++) { ba[t] = __expf(ba[t] - mx); sum += ba[t]; }
        float inv = 1.f / sum;
        float dec = 1.f / (1.f + __expf(-decay_logit[0]));
        float powv = dec, s2 = 0.f;
        float w[8];
        for (int t = 7; t >= 0; t--) {            // t_w[t] = dec^(8-t)
            w[t] = ba[t] * inv * powv;
            powv *= dec;
            s2 += w[t];
        }
        #pragma unroll
        for (int t = 0; t < 8; t++) wsh[t] = w[t];
        ssh = s2;
    }
    __syncthreads();
    float acc = 0.f;
    #pragma unroll
    for (int t = 0; t < 8; t++) acc += wsh[t] * nb[t * Cc + c];
    wbuf[(size_t)r * Cc + c] = acc;
    if (c == 0) svec[r] = ssh;
}

// ---------------- launch ----------------
extern "C" void kernel_launch(void* const* d_in, const int* in_sizes, int n_in,
                              void* d_out, int out_size) {
    (void)in_sizes; (void)n_in; (void)out_size;
    const float* q      = (const float*)d_in[0];
    const float* k      = (const float*)d_in[1];
    const float* v      = (const float*)d_in[2];
    const float* send   = (const float*)d_in[3];
    const float* recv   = (const float*)d_in[4];
    const float* ctrl   = (const float*)d_in[5];
    const float* h      = (const float*)d_in[6];
    const float* buffers= (const float*)d_in[7];
    const float* bond   = (const float*)d_in[8];
    const float* out_w  = (const float*)d_in[9];
    const float* out_b  = (const float*)d_in[10];
    const float* bq_w   = (const float*)d_in[11];
    const float* bq_b   = (const float*)d_in[12];
    const float* bk_w   = (const float*)d_in[13];
    const float* bk_b   = (const float*)d_in[14];
    const float* bv_w   = (const float*)d_in[15];
    const float* bv_b   = (const float*)d_in[16];
    const float* decay  = (const float*)d_in[17];

    float* out     = (float*)d_out;
    float* readout = out;                                   // [N,B,C]
    float* newbuf  = out + (size_t)Rr * Cc;                 // [N,B,T,C]
    float* attn    = newbuf + (size_t)Rr * Tt * Cc;         // [B,H,N,N]

    float *p_msgs, *p_bq, *p_bqk, *p_wbuf, *p_s;
    cudaGetSymbolAddress((void**)&p_msgs, g_msgs);
    cudaGetSymbolAddress((void**)&p_bq,   g_bq);
    cudaGetSymbolAddress((void**)&p_bqk,  g_bqk);
    cudaGetSymbolAddress((void**)&p_wbuf, g_wbuf);
    cudaGetSymbolAddress((void**)&p_s,    g_s);

    const int smem = 3 * 64 * 68 * sizeof(float);           // 52224 B
    cudaFuncSetAttribute(attn_kernel, cudaFuncAttributeMaxDynamicSharedMemorySize, smem);

    attn_kernel<<<Bb * Hh, 256, smem>>>(q, k, v, send, ctrl, bond, p_msgs, attn);
    shift_copy<<<4096, 256>>>((const float4*)buffers, (float4*)newbuf);
    {   EpiMsgs e{out_b, recv, newbuf};
        gemm128<false, EpiMsgs><<<dim3(128, 2), 256>>>(p_msgs, out_w, 256, e); }
    {   EpiBias e{p_bq, bq_b};
        gemm128<false, EpiBias><<<dim3(128, 2), 256>>>(h, bq_w, 128, e); }
    {   EpiPlain e{p_bqk};
        gemm128<true,  EpiPlain><<<dim3(128, 2), 256>>>(p_bq, bk_w, 256, e); }
    temporal_kernel<<<Rr, 256>>>(p_bqk, p_bq, bk_b, newbuf, decay, p_wbuf, p_s);
    {   EpiRead e{readout, bv_b, p_s};
        gemm128<false, EpiRead><<<dim3(128, 2), 256>>>(p_wbuf, bv_w, 256, e); }
}

// round 3
// speedup vs baseline: 1.4157x; 1.4157x over previous
#include <cuda_runtime.h>
#include <cstdint>

#define Nn 64
#define Bb 256
#define Cc 256
#define Hh 4
#define HDd 64
#define Tt 8
#define Mm 128
#define Rr (Nn*Bb)   // 16384 rows

// ---------------- scratch (no allocations allowed) ----------------
__device__ float g_msgs[(size_t)Bb*Nn*Cc];   // [B,N,C] pre-out_w messages
__device__ float g_bqk [(size_t)Rr*Cc];      // [N*B, C]  = bq @ bk_w^T
__device__ float g_wbuf[(size_t)Rr*Cc];      // [N*B, C]  weighted buffer sum
__device__ float g_s   [(size_t)Rr];         // [N*B]     sum of weights
__device__ float g_W2  [(size_t)Mm*Cc];      // bq_w @ bk_w^T
__device__ float g_b2  [Cc];                 // bq_b @ bk_w^T
__device__ float g_u   [Mm + 1];             // bq_w @ bk_b; [128]=bq_b.bk_b

// ============ tiny weight-folding kernels ============
// W2[m][e] = sum_c bq_w[m][c] * bk_w[e][c]
__global__ void fold_w2(const float* __restrict__ bq_w, const float* __restrict__ bk_w,
                        float* __restrict__ W2) {
    __shared__ float Aq[16*64];
    __shared__ float Bk[64*68];
    const int tid = threadIdx.x;
    const int m0 = blockIdx.x * 16;
    const int e0 = blockIdx.y * 64;
    const int e_l = tid & 63, grp = tid >> 6;
    float acc[4] = {0.f, 0.f, 0.f, 0.f};
    for (int c0 = 0; c0 < 256; c0 += 64) {
        {   int row = tid >> 4, col = (tid & 15) * 4;
            *(float4*)&Aq[row*64 + col] =
                *(const float4*)&bq_w[(size_t)(m0 + row) * 256 + c0 + col]; }
        #pragma unroll
        for (int i = 0; i < 4; i++) {
            int t = tid + i * 256;
            int row = t >> 4, col = (t & 15) * 4;
            *(float4*)&Bk[row*68 + col] =
                *(const float4*)&bk_w[(size_t)(e0 + row) * 256 + c0 + col];
        }
        __syncthreads();
        for (int c = 0; c < 64; c++) {
            float bv = Bk[e_l*68 + c];
            #pragma unroll
            for (int i = 0; i < 4; i++) acc[i] += Aq[(grp + 4*i)*64 + c] * bv;
        }
        __syncthreads();
    }
    #pragma unroll
    for (int i = 0; i < 4; i++)
        W2[(size_t)(m0 + grp + 4*i) * 256 + e0 + e_l] = acc[i];
}

// b2[e] = bq_b . bk_w[e][:];  u[m] = bq_w[m][:] . bk_b;  u[128] = bq_b . bk_b
__global__ void fold_small(const float* __restrict__ bq_w, const float* __restrict__ bq_b,
                           const float* __restrict__ bk_w, const float* __restrict__ bk_b,
                           float* __restrict__ b2, float* __restrict__ u) {
    int t = threadIdx.x;  // 256
    float s = 0.f;
    for (int c = 0; c < 256; c++) s += bq_b[c] * bk_w[(size_t)t * 256 + c];
    b2[t] = s;
    if (t < 128) {
        float s2 = 0.f;
        for (int c = 0; c < 256; c++) s2 += bq_w[(size_t)t * 256 + c] * bk_b[c];
        u[t] = s2;
    }
    if (t == 0) {
        float s3 = 0.f;
        for (int c = 0; c < 256; c++) s3 += bq_b[c] * bk_b[c];
        u[128] = s3;
    }
}

// ============ fused graph attention per (b,h) ============
__device__ __forceinline__ unsigned okey(float v) {
    unsigned u = __float_as_uint(v);
    return (u & 0x80000000u) ? ~u : (u | 0x80000000u);
}

__global__ void attn_kernel(const float* __restrict__ q, const float* __restrict__ k,
                            const float* __restrict__ v, const float* __restrict__ sg,
                            const float* __restrict__ ctrl, const float* __restrict__ bond,
                            float* __restrict__ msgs, float* __restrict__ attn_out) {
    extern __shared__ float sm[];
    float* QT = sm;               // [64 d][68]  (Q transposed), later AT[m][n]
    float* KT = sm + 64*68;       // [64 d][68]  (K transposed), later Vs[m][d]
    float* Ls = sm + 2*64*68;     // [64 n][68]  logits

    const int bid = blockIdx.x;
    const int b = bid >> 2;
    const int hh = bid & 3;
    const int tid = threadIdx.x;

    // load Q,K transposed into smem
    #pragma unroll
    for (int i = 0; i < 4; i++) {
        int t = tid + i * 256;
        int row = t >> 4;              // node index
        int col = (t & 15) * 4;        // d
        size_t g = ((size_t)row * Bb + b) * Cc + hh * HDd + col;
        float4 qv = *(const float4*)&q[g];
        float4 kv = *(const float4*)&k[g];
        QT[(col+0)*68 + row] = qv.x; QT[(col+1)*68 + row] = qv.y;
        QT[(col+2)*68 + row] = qv.z; QT[(col+3)*68 + row] = qv.w;
        KT[(col+0)*68 + row] = kv.x; KT[(col+1)*68 + row] = kv.y;
        KT[(col+2)*68 + row] = kv.z; KT[(col+3)*68 + row] = kv.w;
    }
    __syncthreads();

    const int n0 = (tid >> 4) * 4;
    const int m0 = (tid & 15) * 4;

    // logits: Q @ K^T  (outer-product over d)
    float acc[4][4];
    #pragma unroll
    for (int i = 0; i < 4; i++)
        #pragma unroll
        for (int j = 0; j < 4; j++) acc[i][j] = 0.f;
    for (int d = 0; d < 64; d++) {
        float4 a  = *(float4*)&QT[d*68 + n0];
        float4 bv = *(float4*)&KT[d*68 + m0];
        float av[4] = {a.x, a.y, a.z, a.w};
        float bw[4] = {bv.x, bv.y, bv.z, bv.w};
        #pragma unroll
        for (int i = 0; i < 4; i++)
            #pragma unroll
            for (int j = 0; j < 4; j++) acc[i][j] += av[i] * bw[j];
    }
    // epilogue: scale + bond + ctrl + self mask
    float cb[4];
    #pragma unroll
    for (int j = 0; j < 4; j++)
        cb[j] = ctrl[((size_t)(m0 + j) * Bb + b) * Hh + hh];
    #pragma unroll
    for (int i = 0; i < 4; i++) {
        int n = n0 + i;
        float4 bd = *(const float4*)&bond[(size_t)n * Nn + m0];
        float vals[4];
        vals[0] = acc[i][0]*0.125f + bd.x + cb[0];
        vals[1] = acc[i][1]*0.125f + bd.y + cb[1];
        vals[2] = acc[i][2]*0.125f + bd.z + cb[2];
        vals[3] = acc[i][3]*0.125f + bd.w + cb[3];
        int dsel = n - m0;
        if (dsel >= 0 && dsel < 4) vals[dsel] = -1e30f;
        *(float4*)&Ls[n*68 + m0] = *(float4*)vals;
    }
    __syncthreads();

    // load gated V into KT buffer (row-major Vs[m][d]) — KT no longer needed
    #pragma unroll
    for (int i = 0; i < 4; i++) {
        int t = tid + i * 256;
        int row = t >> 4;
        int col = (t & 15) * 4;
        size_t g = ((size_t)row * Bb + b) * Cc + hh * HDd + col;
        float4 vv = *(const float4*)&v[g];
        float4 gg = *(const float4*)&sg[g];
        vv.x *= gg.x; vv.y *= gg.y; vv.z *= gg.z; vv.w *= gg.w;
        *(float4*)&KT[row*68 + col] = vv;
    }

    // warp-parallel exact top-8 + softmax; writes probs to AT (=QT) and attn_out
    const int w = tid >> 5, lane = tid & 31;
    const size_t ao_base = (((size_t)b * Hh + hh) * Nn) * Nn;
    for (int rr = 0; rr < 8; rr++) {
        int row = w * 8 + rr;
        float v0 = Ls[row*68 + lane];
        float v1 = Ls[row*68 + lane + 32];
        float mx = fmaxf(v0, v1);
        #pragma unroll
        for (int o = 16; o > 0; o >>= 1) mx = fmaxf(mx, __shfl_xor_sync(0xffffffffu, mx, o));
        bool s0 = false, s1 = false;
        unsigned long long k0 = ((unsigned long long)okey(v0) << 6) | (unsigned long long)(63 - lane);
        unsigned long long k1 = ((unsigned long long)okey(v1) << 6) | (unsigned long long)(63 - (lane + 32));
        #pragma unroll
        for (int it = 0; it < 8; it++) {
            unsigned long long c0 = s0 ? 0ull : k0;
            unsigned long long c1 = s1 ? 0ull : k1;
            unsigned long long cand = c0 > c1 ? c0 : c1;
            #pragma unroll
            for (int o = 16; o > 0; o >>= 1) {
                unsigned long long other = __shfl_xor_sync(0xffffffffu, cand, o);
                if (other > cand) cand = other;
            }
            int col = 63 - (int)(cand & 63ull);
            if (col == lane) s0 = true;
            else if (col == lane + 32) s1 = true;
        }
        float e0 = s0 ? __expf(v0 - mx) : 0.f;
        float e1 = s1 ? __expf(v1 - mx) : 0.f;
        float ssum = e0 + e1;
        #pragma unroll
        for (int o = 16; o > 0; o >>= 1) ssum += __shfl_xor_sync(0xffffffffu, ssum, o);
        float inv = 1.f / ssum;
        e0 *= inv; e1 *= inv;
        attn_out[ao_base + (size_t)row * Nn + lane]      = e0;
        attn_out[ao_base + (size_t)row * Nn + lane + 32] = e1;
        QT[lane*68 + row]        = e0;   // AT[m][n]
        QT[(lane+32)*68 + row]   = e1;
    }
    __syncthreads();

    // msgs = attn @ Vg (outer-product over m); AT in QT, Vs in KT
    float acc2[4][4];
    #pragma unroll
    for (int i = 0; i < 4; i++)
        #pragma unroll
        for (int j = 0; j < 4; j++) acc2[i][j] = 0.f;
    const int d0 = m0;
    for (int m = 0; m < 64; m++) {
        float4 a  = *(float4*)&QT[m*68 + n0];
        float4 vv = *(float4*)&KT[m*68 + d0];
        float av[4] = {a.x, a.y, a.z, a.w};
        float vw[4] = {vv.x, vv.y, vv.z, vv.w};
        #pragma unroll
        for (int i = 0; i < 4; i++)
            #pragma unroll
            for (int j = 0; j < 4; j++) acc2[i][j] += av[i] * vw[j];
    }
    #pragma unroll
    for (int i = 0; i < 4; i++) {
        size_t o = ((size_t)b * Nn + n0 + i) * Cc + hh * HDd + d0;
        float4 ov = {acc2[i][0], acc2[i][1], acc2[i][2], acc2[i][3]};
        *(float4*)&msgs[o] = ov;
    }
}

// ---------------- buffer shift ----------------
__global__ void shift_copy(const float4* __restrict__ src, float4* __restrict__ dst) {
    const long total = (long)Rr * 7 * 64;
    for (long i = (long)blockIdx.x * blockDim.x + threadIdx.x; i < total;
         i += (long)gridDim.x * blockDim.x) {
        long c4 = i & 63;
        long t  = (i >> 6) % 7;
        long r  = i / (7 * 64);
        dst[(r * 8 + t) * 64 + c4] = src[(r * 8 + t + 1) * 64 + c4];
    }
}

// ============ pipelined SGEMM 128x128 tile with cp.async double buffering ============
__device__ __forceinline__ void cpa8(uint32_t s, const float* g) {
    asm volatile("cp.async.ca.shared.global [%0], [%1], 8;" :: "r"(s), "l"(g));
}
__device__ __forceinline__ void cpa16(uint32_t s, const float* g) {
    asm volatile("cp.async.ca.shared.global [%0], [%1], 16;" :: "r"(s), "l"(g));
}

struct EpiMsgs {   // bias + recv gate, write into new_buf slot T-1
    const float* out_b; const float* recv; float* nb;
    __device__ __forceinline__ void store(int r, int c, float acc) const {
        int n = r & 63, b = r >> 6;
        size_t rb = (size_t)n * Bb + b;
        float val = (acc + out_b[c]) * recv[rb * Cc + c];
        nb[(rb * Tt + (Tt - 1)) * Cc + c] = val;
    }
};
struct EpiBias {
    float* out; const float* bias;
    __device__ __forceinline__ void store(int r, int c, float acc) const {
        out[(size_t)r * Cc + c] = acc + bias[c];
    }
};
struct EpiRead {
    float* out; const float* bias; const float* s;
    __device__ __forceinline__ void store(int r, int c, float acc) const {
        out[(size_t)r * Cc + c] = acc + s[r] * bias[c];
    }
};

template<typename Epi>
__global__ void __launch_bounds__(256, 2)
gemm128p(const float* __restrict__ A, const float* __restrict__ Bw, int K, Epi epi) {
    __shared__ float As[2][128*18];   // row-major [row][k], pitch 18
    __shared__ float Bs[2][16*132];   // row-major [k][col], pitch 132
    const int tid = threadIdx.x;
    const int tx = tid & 15, ty = tid >> 4;
    const int r0 = blockIdx.x * 128, c0 = blockIdx.y * 128;
    const uint32_t sA = (uint32_t)__cvta_generic_to_shared(&As[0][0]);
    const uint32_t sB = (uint32_t)__cvta_generic_to_shared(&Bs[0][0]);
    const int NS = K >> 4;

    float acc[8][8];
    #pragma unroll
    for (int i = 0; i < 8; i++)
        #pragma unroll
        for (int j = 0; j < 8; j++) acc[i][j] = 0.f;

    {   // prefetch stage 0
        const float* Agp = A + (size_t)r0 * K;
        #pragma unroll
        for (int i = 0; i < 4; i++) {
            int ch = tid + i * 256;
            int row = ch >> 3, cp = (ch & 7) * 2;
            cpa8(sA + (uint32_t)((row*18 + cp) * 4), Agp + (size_t)row * K + cp);
        }
        const float* Bgp = Bw + c0;
        #pragma unroll
        for (int i = 0; i < 2; i++) {
            int ch = tid + i * 256;
            int kr = ch >> 5, cp = (ch & 31) * 4;
            cpa16(sB + (uint32_t)((kr*132 + cp) * 4), Bgp + (size_t)kr * Cc + cp);
        }
        asm volatile("cp.async.commit_group;");
    }

    for (int s = 0; s < NS; s++) {
        if (s + 1 < NS) {
            int buf = (s + 1) & 1;
            const float* Agp = A + (size_t)r0 * K + (s + 1) * 16;
            #pragma unroll
            for (int i = 0; i < 4; i++) {
                int ch = tid + i * 256;
                int row = ch >> 3, cp = (ch & 7) * 2;
                cpa8(sA + (uint32_t)((buf*128*18 + row*18 + cp) * 4), Agp + (size_t)row * K + cp);
            }
            const float* Bgp = Bw + (size_t)((s + 1) * 16) * Cc + c0;
            #pragma unroll
            for (int i = 0; i < 2; i++) {
                int ch = tid + i * 256;
                int kr = ch >> 5, cp = (ch & 31) * 4;
                cpa16(sB + (uint32_t)((buf*16*132 + kr*132 + cp) * 4), Bgp + (size_t)kr * Cc + cp);
            }
            asm volatile("cp.async.commit_group;");
            asm volatile("cp.async.wait_group 1;");
        } else {
            asm volatile("cp.async.wait_group 0;");
        }
        __syncthreads();
        const float* Ap = &As[s & 1][0];
        const float* Bp = &Bs[s & 1][0];
        #pragma unroll
        for (int kk = 0; kk < 16; kk++) {
            float a[8], bb[8];
            #pragma unroll
            for (int i = 0; i < 8; i++) a[i] = Ap[(ty*8 + i)*18 + kk];
            *(float4*)&bb[0] = *(const float4*)&Bp[kk*132 + tx*8];
            *(float4*)&bb[4] = *(const float4*)&Bp[kk*132 + tx*8 + 4];
            #pragma unroll
            for (int i = 0; i < 8; i++)
                #pragma unroll
                for (int j = 0; j < 8; j++) acc[i][j] += a[i] * bb[j];
        }
        __syncthreads();
    }
    #pragma unroll
    for (int i = 0; i < 8; i++)
        #pragma unroll
        for (int j = 0; j < 8; j++)
            epi.store(r0 + ty*8 + i, c0 + tx*8 + j, acc[i][j]);
}

// ---------------- temporal: ba softmax + weighted buffer sum ----------------
__global__ void temporal_kernel(const float* __restrict__ bqk,
                                const float* __restrict__ h,
                                const float* __restrict__ u,
                                const float* __restrict__ newbuf,
                                const float* __restrict__ decay_logit,
                                float* __restrict__ wbuf,
                                float* __restrict__ svec) {
    const int r = blockIdx.x;            // r = n*B + b
    const int c = threadIdx.x;           // 0..255
    const float* nb = newbuf + (size_t)r * (Tt * Cc);

    float qk = bqk[(size_t)r * Cc + c];
    float nbv[8];
    float p[9];
    #pragma unroll
    for (int t = 0; t < 8; t++) { nbv[t] = nb[t * Cc + c]; p[t] = qk * nbv[t]; }
    p[8] = (c < Mm) ? h[(size_t)r * Mm + c] * u[c] : 0.f;

    #pragma unroll
    for (int t = 0; t < 9; t++)
        #pragma unroll
        for (int o = 16; o > 0; o >>= 1)
            p[t] += __shfl_xor_sync(0xffffffffu, p[t], o);

    __shared__ float red[8][9];
    __shared__ float wsh[8];
    __shared__ float ssh;
    int warp = c >> 5, lane = c & 31;
    if (lane == 0) {
        #pragma unroll
        for (int t = 0; t < 9; t++) red[warp][t] = p[t];
    }
    __syncthreads();
    if (c == 0) {
        float bqb = u[128];               // s0 = bq_b . bk_b
        #pragma unroll
        for (int w = 0; w < 8; w++) bqb += red[w][8];
        float ba[8]; float mx = -3e38f;
        #pragma unroll
        for (int t = 0; t < 8; t++) {
            float s = 0.f;
            #pragma unroll
            for (int w = 0; w < 8; w++) s += red[w][t];
            ba[t] = (s + bqb) * 0.0625f;
            mx = fmaxf(mx, ba[t]);
        }
        float sum = 0.f;
        #pragma unroll
        for (int t = 0; t < 8; t++) { ba[t] = __expf(ba[t] - mx); sum += ba[t]; }
        float inv = 1.f / sum;
        float dec = 1.f / (1.f + __expf(-decay_logit[0]));
        float powv = dec, s2 = 0.f;
        float wv[8];
        for (int t = 7; t >= 0; t--) {
            wv[t] = ba[t] * inv * powv;
            powv *= dec;
            s2 += wv[t];
        }
        #pragma unroll
        for (int t = 0; t < 8; t++) wsh[t] = wv[t];
        ssh = s2;
    }
    __syncthreads();
    float acc = 0.f;
    #pragma unroll
    for (int t = 0; t < 8; t++) acc += wsh[t] * nbv[t];
    wbuf[(size_t)r * Cc + c] = acc;
    if (c == 0) svec[r] = ssh;
}

// ---------------- launch ----------------
extern "C" void kernel_launch(void* const* d_in, const int* in_sizes, int n_in,
                              void* d_out, int out_size) {
    (void)in_sizes; (void)n_in; (void)out_size;
    const float* q      = (const float*)d_in[0];
    const float* k      = (const float*)d_in[1];
    const float* v      = (const float*)d_in[2];
    const float* send   = (const float*)d_in[3];
    const float* recv   = (const float*)d_in[4];
    const float* ctrl   = (const float*)d_in[5];
    const float* h      = (const float*)d_in[6];
    const float* buffers= (const float*)d_in[7];
    const float* bond   = (const float*)d_in[8];
    const float* out_w  = (const float*)d_in[9];
    const float* out_b  = (const float*)d_in[10];
    const float* bq_w   = (const float*)d_in[11];
    const float* bq_b   = (const float*)d_in[12];
    const float* bk_w   = (const float*)d_in[13];
    const float* bk_b   = (const float*)d_in[14];
    const float* bv_w   = (const float*)d_in[15];
    const float* bv_b   = (const float*)d_in[16];
    const float* decay  = (const float*)d_in[17];

    float* out     = (float*)d_out;
    float* readout = out;                                   // [N,B,C]
    float* newbuf  = out + (size_t)Rr * Cc;                 // [N,B,T,C]
    float* attn    = newbuf + (size_t)Rr * Tt * Cc;         // [B,H,N,N]

    float *p_msgs, *p_bqk, *p_wbuf, *p_s, *p_W2, *p_b2, *p_u;
    cudaGetSymbolAddress((void**)&p_msgs, g_msgs);
    cudaGetSymbolAddress((void**)&p_bqk,  g_bqk);
    cudaGetSymbolAddress((void**)&p_wbuf, g_wbuf);
    cudaGetSymbolAddress((void**)&p_s,    g_s);
    cudaGetSymbolAddress((void**)&p_W2,   g_W2);
    cudaGetSymbolAddress((void**)&p_b2,   g_b2);
    cudaGetSymbolAddress((void**)&p_u,    g_u);

    const int smem = 3 * 64 * 68 * sizeof(float);           // 52224 B
    cudaFuncSetAttribute(attn_kernel, cudaFuncAttributeMaxDynamicSharedMemorySize, smem);

    // independent precomputes first
    fold_w2<<<dim3(8, 4), 256>>>(bq_w, bk_w, p_W2);
    fold_small<<<1, 256>>>(bq_w, bq_b, bk_w, bk_b, p_b2, p_u);
    shift_copy<<<4096, 256>>>((const float4*)buffers, (float4*)newbuf);
    attn_kernel<<<Bb * Hh, 256, smem>>>(q, k, v, send, ctrl, bond, p_msgs, attn);

    {   EpiMsgs e{out_b, recv, newbuf};
        gemm128p<EpiMsgs><<<dim3(128, 2), 256>>>(p_msgs, out_w, 256, e); }
    {   EpiBias e{p_bqk, p_b2};
        gemm128p<EpiBias><<<dim3(128, 2), 256>>>(h, p_W2, 128, e); }
    temporal_kernel<<<Rr, 256>>>(p_bqk, h, p_u, newbuf, decay, p_wbuf, p_s);
    {   EpiRead e{readout, bv_b, p_s};
        gemm128p<EpiRead><<<dim3(128, 2), 256>>>(p_wbuf, bv_w, 256, e); }
}

// round 5
// speedup vs baseline: 1.8634x; 1.3162x over previous
#include <cuda_runtime.h>
#include <cuda_bf16.h>
#include <cstdint>

#define Nn 64
#define Bb 256
#define Cc 256
#define Hh 4
#define HDd 64
#define Tt 8
#define Mm 128
#define Rr (Nn*Bb)   // 16384 rows

// ---------------- scratch (no allocations allowed) ----------------
__device__ __nv_bfloat16 g_msh[(size_t)Rr*Cc];   // msgs hi  [B*N, 256]
__device__ __nv_bfloat16 g_msl[(size_t)Rr*Cc];   // msgs lo
__device__ __nv_bfloat16 g_wbh[(size_t)Rr*Cc];   // wbuf hi  [N*B, 256]
__device__ __nv_bfloat16 g_wbl[(size_t)Rr*Cc];   // wbuf lo
__device__ __nv_bfloat16 g_hh [(size_t)Rr*Mm];   // h hi     [N*B, 128]
__device__ __nv_bfloat16 g_hl [(size_t)Rr*Mm];   // h lo
__device__ __nv_bfloat16 g_owt_h[(size_t)Cc*Cc]; // out_w^T hi  [n][k]
__device__ __nv_bfloat16 g_owt_l[(size_t)Cc*Cc];
__device__ __nv_bfloat16 g_bvt_h[(size_t)Cc*Cc]; // bv_w^T hi
__device__ __nv_bfloat16 g_bvt_l[(size_t)Cc*Cc];
__device__ __nv_bfloat16 g_w2t_h[(size_t)Cc*Mm]; // (bq_w@bk_w^T)^T hi [e][m]
__device__ __nv_bfloat16 g_w2t_l[(size_t)Cc*Mm];
__device__ float g_bqk [(size_t)Rr*Cc];          // [N*B, C]
__device__ float g_s   [(size_t)Rr];
__device__ float g_b2  [Cc];                     // bq_b @ bk_w^T
__device__ float g_u   [Mm + 1];                 // bq_w @ bk_b; [128]=bq_b.bk_b

// ================= helpers =================
__device__ __forceinline__ void bsplit(float x, __nv_bfloat16& hi, __nv_bfloat16& lo) {
    hi = __float2bfloat16(x);
    lo = __float2bfloat16(x - __bfloat162float(hi));
}
__device__ __forceinline__ uint32_t smem_u32(const void* p) {
    uint32_t a;
    asm("{ .reg .u64 t; cvta.to.shared.u64 t, %1; cvt.u32.u64 %0, t; }" : "=r"(a) : "l"(p));
    return a;
}
__device__ __forceinline__ void cp16(uint32_t d, const void* s) {
    asm volatile("cp.async.ca.shared.global [%0], [%1], 16;" :: "r"(d), "l"(s));
}
__device__ __forceinline__ void ldsm4(uint32_t* r, uint32_t a) {
    asm volatile("ldmatrix.sync.aligned.m8n8.x4.shared.b16 {%0,%1,%2,%3}, [%4];"
                 : "=r"(r[0]), "=r"(r[1]), "=r"(r[2]), "=r"(r[3]) : "r"(a));
}
__device__ __forceinline__ void mma16816(float* d, const uint32_t* a, const uint32_t* b) {
    asm volatile("mma.sync.aligned.m16n8k16.row.col.f32.bf16.bf16.f32 "
                 "{%0,%1,%2,%3}, {%4,%5,%6,%7}, {%8,%9}, {%0,%1,%2,%3};"
                 : "+f"(d[0]), "+f"(d[1]), "+f"(d[2]), "+f"(d[3])
                 : "r"(a[0]), "r"(a[1]), "r"(a[2]), "r"(a[3]), "r"(b[0]), "r"(b[1]));
}

// ============ weight folding ============
__global__ void fold_w2(const float* __restrict__ bq_w, const float* __restrict__ bk_w,
                        __nv_bfloat16* __restrict__ W2th, __nv_bfloat16* __restrict__ W2tl) {
    __shared__ float Aq[16*64];
    __shared__ float Bk[64*68];
    const int tid = threadIdx.x;
    const int m0 = blockIdx.x * 16;
    const int e0 = blockIdx.y * 64;
    const int e_l = tid & 63, grp = tid >> 6;
    float acc[4] = {0.f, 0.f, 0.f, 0.f};
    for (int c0 = 0; c0 < 256; c0 += 64) {
        {   int row = tid >> 4, col = (tid & 15) * 4;
            *(float4*)&Aq[row*64 + col] =
                *(const float4*)&bq_w[(size_t)(m0 + row) * 256 + c0 + col]; }
        #pragma unroll
        for (int i = 0; i < 4; i++) {
            int t = tid + i * 256;
            int row = t >> 4, col = (t & 15) * 4;
            *(float4*)&Bk[row*68 + col] =
                *(const float4*)&bk_w[(size_t)(e0 + row) * 256 + c0 + col];
        }
        __syncthreads();
        for (int c = 0; c < 64; c++) {
            float bv = Bk[e_l*68 + c];
            #pragma unroll
            for (int i = 0; i < 4; i++) acc[i] += Aq[(grp + 4*i)*64 + c] * bv;
        }
        __syncthreads();
    }
    #pragma unroll
    for (int i = 0; i < 4; i++) {
        __nv_bfloat16 hi, lo; bsplit(acc[i], hi, lo);
        size_t o = (size_t)(e0 + e_l) * Mm + (m0 + grp + 4*i);   // transposed [e][m]
        W2th[o] = hi; W2tl[o] = lo;
    }
}

__global__ void fold_small(const float* __restrict__ bq_w, const float* __restrict__ bq_b,
                           const float* __restrict__ bk_w, const float* __restrict__ bk_b,
                           float* __restrict__ b2, float* __restrict__ u) {
    int t = threadIdx.x;
    float s = 0.f;
    for (int c = 0; c < 256; c++) s += bq_b[c] * bk_w[(size_t)t * 256 + c];
    b2[t] = s;
    if (t < 128) {
        float s2 = 0.f;
        for (int c = 0; c < 256; c++) s2 += bq_w[(size_t)t * 256 + c] * bk_b[c];
        u[t] = s2;
    }
    if (t == 0) {
        float s3 = 0.f;
        for (int c = 0; c < 256; c++) s3 += bq_b[c] * bk_b[c];
        u[128] = s3;
    }
}

// split h [N*B,128] into bf16 hi/lo
__global__ void split_h(const float* __restrict__ h, __nv_bfloat16* __restrict__ hh,
                        __nv_bfloat16* __restrict__ hl) {
    size_t i = (size_t)blockIdx.x * blockDim.x + threadIdx.x;
    __nv_bfloat16 hi, lo; bsplit(h[i], hi, lo);
    hh[i] = hi; hl[i] = lo;
}

// transpose + split a 256x256 weight: out[n][k] = bf16split(W[k][n])
__global__ void wsplit_t(const float* __restrict__ W, __nv_bfloat16* __restrict__ th,
                         __nv_bfloat16* __restrict__ tl) {
    __shared__ float tile[32][33];
    const int bx = blockIdx.x, by = blockIdx.y;
    const int tx = threadIdx.x & 31, ty0 = threadIdx.x >> 5;
    #pragma unroll
    for (int i = 0; i < 4; i++) {
        int kk = by*32 + ty0 + i*8;
        tile[ty0 + i*8][tx] = W[(size_t)kk * 256 + bx*32 + tx];
    }
    __syncthreads();
    #pragma unroll
    for (int i = 0; i < 4; i++) {
        int n = bx*32 + ty0 + i*8;
        int kk = by*32 + tx;
        __nv_bfloat16 hi, lo; bsplit(tile[tx][ty0 + i*8], hi, lo);
        th[(size_t)n*256 + kk] = hi; tl[(size_t)n*256 + kk] = lo;
    }
}

// ============ fused graph attention per (b,h) ============
__device__ __forceinline__ unsigned okey(float v) {
    unsigned u = __float_as_uint(v);
    return (u & 0x80000000u) ? ~u : (u | 0x80000000u);
}

__global__ void attn_kernel(const float* __restrict__ q, const float* __restrict__ k,
                            const float* __restrict__ v, const float* __restrict__ sg,
                            const float* __restrict__ ctrl, const float* __restrict__ bond,
                            __nv_bfloat16* __restrict__ msh, __nv_bfloat16* __restrict__ msl,
                            float* __restrict__ attn_out) {
    extern __shared__ float sm[];
    float* QT = sm;               // [64 d][68]  Q^T, later A^T[m][n]
    float* KT = sm + 64*68;       // [64 d][68]  K^T, later Vs[m][d]
    float* Ls = sm + 2*64*68;     // [64 n][68]  logits

    const int bid = blockIdx.x;
    const int b = bid >> 2;
    const int hh = bid & 3;
    const int tid = threadIdx.x;

    #pragma unroll
    for (int i = 0; i < 4; i++) {
        int t = tid + i * 256;
        int row = t >> 4;
        int col = (t & 15) * 4;
        size_t g = ((size_t)row * Bb + b) * Cc + hh * HDd + col;
        float4 qv = *(const float4*)&q[g];
        float4 kv = *(const float4*)&k[g];
        QT[(col+0)*68 + row] = qv.x; QT[(col+1)*68 + row] = qv.y;
        QT[(col+2)*68 + row] = qv.z; QT[(col+3)*68 + row] = qv.w;
        KT[(col+0)*68 + row] = kv.x; KT[(col+1)*68 + row] = kv.y;
        KT[(col+2)*68 + row] = kv.z; KT[(col+3)*68 + row] = kv.w;
    }
    __syncthreads();

    const int n0 = (tid >> 4) * 4;
    const int m0 = (tid & 15) * 4;

    float acc[4][4];
    #pragma unroll
    for (int i = 0; i < 4; i++)
        #pragma unroll
        for (int j = 0; j < 4; j++) acc[i][j] = 0.f;
    for (int d = 0; d < 64; d++) {
        float4 a  = *(float4*)&QT[d*68 + n0];
        float4 bv = *(float4*)&KT[d*68 + m0];
        float av[4] = {a.x, a.y, a.z, a.w};
        float bw[4] = {bv.x, bv.y, bv.z, bv.w};
        #pragma unroll
        for (int i = 0; i < 4; i++)
            #pragma unroll
            for (int j = 0; j < 4; j++) acc[i][j] += av[i] * bw[j];
    }
    float cb[4];
    #pragma unroll
    for (int j = 0; j < 4; j++)
        cb[j] = ctrl[((size_t)(m0 + j) * Bb + b) * Hh + hh];
    #pragma unroll
    for (int i = 0; i < 4; i++) {
        int n = n0 + i;
        float4 bd = *(const float4*)&bond[(size_t)n * Nn + m0];
        float vals[4];
        vals[0] = acc[i][0]*0.125f + bd.x + cb[0];
        vals[1] = acc[i][1]*0.125f + bd.y + cb[1];
        vals[2] = acc[i][2]*0.125f + bd.z + cb[2];
        vals[3] = acc[i][3]*0.125f + bd.w + cb[3];
        int dsel = n - m0;
        if (dsel >= 0 && dsel < 4) vals[dsel] = -1e30f;
        *(float4*)&Ls[n*68 + m0] = *(float4*)vals;
    }
    __syncthreads();

    // load gated V into KT (row-major Vs[m][d])
    #pragma unroll
    for (int i = 0; i < 4; i++) {
        int t = tid + i * 256;
        int row = t >> 4;
        int col = (t & 15) * 4;
        size_t g = ((size_t)row * Bb + b) * Cc + hh * HDd + col;
        float4 vv = *(const float4*)&v[g];
        float4 gg = *(const float4*)&sg[g];
        vv.x *= gg.x; vv.y *= gg.y; vv.z *= gg.z; vv.w *= gg.w;
        *(float4*)&KT[row*68 + col] = vv;
    }

    // warp-parallel exact top-8 (REDUX + ballot, lowest-index tie-break) + softmax
    const int w = tid >> 5, lane = tid & 31;
    const size_t ao_base = (((size_t)b * Hh + hh) * Nn) * Nn;
    for (int rr = 0; rr < 8; rr++) {
        int row = w * 8 + rr;
        float v0 = Ls[row*68 + lane];
        float v1 = Ls[row*68 + lane + 32];
        unsigned k0 = okey(v0), k1 = okey(v1);
        bool s0 = false, s1 = false;
        float mx = 0.f;
        #pragma unroll
        for (int it = 0; it < 8; it++) {
            unsigned c0 = s0 ? 0u : k0;
            unsigned c1 = s1 ? 0u : k1;
            unsigned m = c0 > c1 ? c0 : c1;
            unsigned best = __reduce_max_sync(0xffffffffu, m);
            if (it == 0)
                mx = __uint_as_float((best & 0x80000000u) ? (best & 0x7fffffffu) : ~best);
            unsigned b0 = __ballot_sync(0xffffffffu, c0 == best);
            if (b0) {
                if (lane == __ffs(b0) - 1) s0 = true;
            } else {
                unsigned b1 = __ballot_sync(0xffffffffu, c1 == best);
                if (lane == __ffs(b1) - 1) s1 = true;
            }
        }
        float e0 = s0 ? __expf(v0 - mx) : 0.f;
        float e1 = s1 ? __expf(v1 - mx) : 0.f;
        float ssum = e0 + e1;
        #pragma unroll
        for (int o = 16; o > 0; o >>= 1) ssum += __shfl_xor_sync(0xffffffffu, ssum, o);
        float inv = 1.f / ssum;
        e0 *= inv; e1 *= inv;
        attn_out[ao_base + (size_t)row * Nn + lane]      = e0;
        attn_out[ao_base + (size_t)row * Nn + lane + 32] = e1;
        QT[lane*68 + row]      = e0;    // A^T[m][n]
        QT[(lane+32)*68 + row] = e1;
    }
    __syncthreads();

    // msgs = attn @ Vg; write bf16 hi/lo splits
    float acc2[4][4];
    #pragma unroll
    for (int i = 0; i < 4; i++)
        #pragma unroll
        for (int j = 0; j < 4; j++) acc2[i][j] = 0.f;
    const int d0 = m0;
    for (int m = 0; m < 64; m++) {
        float4 a  = *(float4*)&QT[m*68 + n0];
        float4 vv = *(float4*)&KT[m*68 + d0];
        float av[4] = {a.x, a.y, a.z, a.w};
        float vw[4] = {vv.x, vv.y, vv.z, vv.w};
        #pragma unroll
        for (int i = 0; i < 4; i++)
            #pragma unroll
            for (int j = 0; j < 4; j++) acc2[i][j] += av[i] * vw[j];
    }
    #pragma unroll
    for (int i = 0; i < 4; i++) {
        size_t o = ((size_t)b * Nn + n0 + i) * Cc + hh * HDd + d0;
        __nv_bfloat16 hi[4], lo[4];
        #pragma unroll
        for (int j = 0; j < 4; j++) bsplit(acc2[i][j], hi[j], lo[j]);
        __nv_bfloat162 h01, h23, l01, l23;
        h01.x = hi[0]; h01.y = hi[1]; h23.x = hi[2]; h23.y = hi[3];
        l01.x = lo[0]; l01.y = lo[1]; l23.x = lo[2]; l23.y = lo[3];
        *(__nv_bfloat162*)&msh[o]     = h01;
        *(__nv_bfloat162*)&msh[o + 2] = h23;
        *(__nv_bfloat162*)&msl[o]     = l01;
        *(__nv_bfloat162*)&msl[o + 2] = l23;
    }
}

// ---------------- buffer shift ----------------
__global__ void shift_copy(const float4* __restrict__ src, float4* __restrict__ dst) {
    const long total = (long)Rr * 7 * 64;
    for (long i = (long)blockIdx.x * blockDim.x + threadIdx.x; i < total;
         i += (long)gridDim.x * blockDim.x) {
        long c4 = i & 63;
        long t  = (i >> 6) % 7;
        long r  = i / (7 * 64);
        dst[(r * 8 + t) * 64 + c4] = src[(r * 8 + t + 1) * 64 + c4];
    }
}

// ============ split-bf16 HMMA GEMM: [16384 x K] @ [K x 256] ============
// A as bf16 hi/lo [rows x K]; B TRANSPOSED hi/lo [256(N) x K].
// D = Ah*Bh^T + Ah*Bl^T + Al*Bh^T, fp32 accumulate via mma.sync m16n8k16.
struct EpiMsgs {   // (acc + out_b[c]) * recv -> newbuf slot T-1
    const float* out_b; const float* recv; float* nb;
    __device__ __forceinline__ void store(int r, int c, float acc) const {
        int n = r & 63, b = r >> 6;
        size_t rb = (size_t)n * Bb + b;
        float val = (acc + out_b[c]) * recv[rb * Cc + c];
        nb[(rb * Tt + (Tt - 1)) * Cc + c] = val;
    }
};
struct EpiBias {
    float* out; const float* bias;
    __device__ __forceinline__ void store(int r, int c, float acc) const {
        out[(size_t)r * Cc + c] = acc + bias[c];
    }
};
struct EpiRead {
    float* out; const float* bias; const float* s;
    __device__ __forceinline__ void store(int r, int c, float acc) const {
        out[(size_t)r * Cc + c] = acc + s[r] * bias[c];
    }
};

// smem: A [2 buf][2 split][128 rows][40 bf16]  = 40960 B
//       B [2 buf][2 split][ 64 rows][40 bf16]  = 20480 B
#define GEMM_SMEM (40960 + 20480)

template<typename Epi>
__global__ void __launch_bounds__(256, 2)
gemm_mma(const __nv_bfloat16* __restrict__ Ah, const __nv_bfloat16* __restrict__ Al,
         const __nv_bfloat16* __restrict__ Bth, const __nv_bfloat16* __restrict__ Btl,
         int K, Epi epi) {
    extern __shared__ char smem[];
    const uint32_t sbA = smem_u32(smem);
    const uint32_t sbB = sbA + 40960;
    const int tid = threadIdx.x, wid = tid >> 5, lane = tid & 31;
    const int r0 = blockIdx.x * 128, c0 = blockIdx.y * 64;
    const int wm = (wid & 3) * 32, wn = (wid >> 2) * 32;
    const int NS = K >> 5;            // 32-wide K stages

    float acc[2][4][4];
    #pragma unroll
    for (int mt = 0; mt < 2; mt++)
        #pragma unroll
        for (int nt = 0; nt < 4; nt++)
            #pragma unroll
            for (int j = 0; j < 4; j++) acc[mt][nt][j] = 0.f;

    auto loadChunk = [&](int stage, int buf) {
        const char* srcAh = (const char*)(Ah + (size_t)r0 * K + stage * 32);
        const char* srcAl = (const char*)(Al + (size_t)r0 * K + stage * 32);
        #pragma unroll
        for (int i = 0; i < 4; i++) {
            int ch = tid + i * 256;              // 0..1023
            int s = ch >> 9;
            int rem = ch & 511;
            int row = rem >> 2, seg = rem & 3;
            uint32_t dst = sbA + (uint32_t)(((buf*2 + s)*128 + row) * 80 + seg * 16);
            const char* src = (s ? srcAl : srcAh) + (size_t)row * (K * 2) + seg * 16;
            cp16(dst, src);
        }
        const char* srcBh = (const char*)(Bth + (size_t)c0 * K + stage * 32);
        const char* srcBl = (const char*)(Btl + (size_t)c0 * K + stage * 32);
        #pragma unroll
        for (int i = 0; i < 2; i++) {
            int ch = tid + i * 256;              // 0..511
            int s = ch >> 8;
            int rem = ch & 255;
            int row = rem >> 2, seg = rem & 3;
            uint32_t dst = sbB + (uint32_t)(((buf*2 + s)*64 + row) * 80 + seg * 16);
            const char* src = (s ? srcBl : srcBh) + (size_t)row * (K * 2) + seg * 16;
            cp16(dst, src);
        }
        asm volatile("cp.async.commit_group;");
    };

    loadChunk(0, 0);

    const int lg = lane >> 3, lr = lane & 7;

    for (int i = 0; i < NS; i++) {
        if (i + 1 < NS) {
            loadChunk(i + 1, (i + 1) & 1);
            asm volatile("cp.async.wait_group 1;");
        } else {
            asm volatile("cp.async.wait_group 0;");
        }
        __syncthreads();
        int buf = i & 1;
        #pragma unroll
        for (int kk = 0; kk < 2; kk++) {
            uint32_t Af[2][2][4];   // [split][mtile][4]
            uint32_t Bf[2][4][2];   // [split][ntile][2]
            #pragma unroll
            for (int s = 0; s < 2; s++)
                #pragma unroll
                for (int mt = 0; mt < 2; mt++) {
                    int row = wm + mt*16 + (lg & 1)*8 + lr;
                    int kc  = kk*16 + (lg >> 1)*8;
                    ldsm4(Af[s][mt], sbA + (uint32_t)(((buf*2 + s)*128 + row)*80 + kc*2));
                }
            #pragma unroll
            for (int s = 0; s < 2; s++)
                #pragma unroll
                for (int nt2 = 0; nt2 < 2; nt2++) {
                    int row = wn + nt2*16 + (lg >> 1)*8 + lr;
                    int kc  = kk*16 + (lg & 1)*8;
                    uint32_t r[4];
                    ldsm4(r, sbB + (uint32_t)(((buf*2 + s)*64 + row)*80 + kc*2));
                    Bf[s][nt2*2][0]   = r[0]; Bf[s][nt2*2][1]   = r[1];
                    Bf[s][nt2*2+1][0] = r[2]; Bf[s][nt2*2+1][1] = r[3];
                }
            #pragma unroll
            for (int mt = 0; mt < 2; mt++)
                #pragma unroll
                for (int nt = 0; nt < 4; nt++) {
                    mma16816(acc[mt][nt], Af[0][mt], Bf[0][nt]);
                    mma16816(acc[mt][nt], Af[0][mt], Bf[1][nt]);
                    mma16816(acc[mt][nt], Af[1][mt], Bf[0][nt]);
                }
        }
        __syncthreads();
    }

    // epilogue: d0,d1 = (row g, col 2tg, 2tg+1); d2,d3 = row g+8
    const int g = lane >> 2, tg = lane & 3;
    #pragma unroll
    for (int mt = 0; mt < 2; mt++)
        #pragma unroll
        for (int nt = 0; nt < 4; nt++) {
            int row = r0 + wm + mt*16 + g;
            int col = c0 + wn + nt*8 + tg*2;
            epi.store(row,     col,     acc[mt][nt][0]);
            epi.store(row,     col + 1, acc[mt][nt][1]);
            epi.store(row + 8, col,     acc[mt][nt][2]);
            epi.store(row + 8, col + 1, acc[mt][nt][3]);
        }
}

// ---------------- temporal: ba softmax + weighted buffer sum (emits bf16 splits) ----------------
__global__ void temporal_kernel(const float* __restrict__ bqk,
                                const float* __restrict__ h,
                                const float* __restrict__ u,
                                const float* __restrict__ newbuf,
                                const float* __restrict__ decay_logit,
                                __nv_bfloat16* __restrict__ wbh,
                                __nv_bfloat16* __restrict__ wbl,
                                float* __restrict__ svec) {
    const int r = blockIdx.x;            // r = n*B + b
    const int c = threadIdx.x;           // 0..255
    const float* nb = newbuf + (size_t)r * (Tt * Cc);

    float qk = bqk[(size_t)r * Cc + c];
    float nbv[8];
    float p[9];
    #pragma unroll
    for (int t = 0; t < 8; t++) { nbv[t] = nb[t * Cc + c]; p[t] = qk * nbv[t]; }
    p[8] = (c < Mm) ? h[(size_t)r * Mm + c] * u[c] : 0.f;

    #pragma unroll
    for (int t = 0; t < 9; t++)
        #pragma unroll
        for (int o = 16; o > 0; o >>= 1)
            p[t] += __shfl_xor_sync(0xffffffffu, p[t], o);

    __shared__ float red[8][9];
    __shared__ float wsh[8];
    __shared__ float ssh;
    int warp = c >> 5, lane = c & 31;
    if (lane == 0) {
        #pragma unroll
        for (int t = 0; t < 9; t++) red[warp][t] = p[t];
    }
    __syncthreads();
    if (c == 0) {
        float bqb = u[128];
        #pragma unroll
        for (int w = 0; w < 8; w++) bqb += red[w][8];
        float ba[8]; float mx = -3e38f;
        #pragma unroll
        for (int t = 0; t < 8; t++) {
            float s = 0.f;
            #pragma unroll
            for (int w = 0; w < 8; w++) s += red[w][t];
            ba[t] = (s + bqb) * 0.0625f;
            mx = fmaxf(mx, ba[t]);
        }
        float sum = 0.f;
        #pragma unroll
        for (int t = 0; t < 8; t++) { ba[t] = __expf(ba[t] - mx); sum += ba[t]; }
        float inv = 1.f / sum;
        float dec = 1.f / (1.f + __expf(-decay_logit[0]));
        float powv = dec, s2 = 0.f;
        float wv[8];
        for (int t = 7; t >= 0; t--) {
            wv[t] = ba[t] * inv * powv;
            powv *= dec;
            s2 += wv[t];
        }
        #pragma unroll
        for (int t = 0; t < 8; t++) wsh[t] = wv[t];
        ssh = s2;
    }
    __syncthreads();
    float acc = 0.f;
    #pragma unroll
    for (int t = 0; t < 8; t++) acc += wsh[t] * nbv[t];
    __nv_bfloat16 hi, lo; bsplit(acc, hi, lo);
    wbh[(size_t)r * Cc + c] = hi;
    wbl[(size_t)r * Cc + c] = lo;
    if (c == 0) svec[r] = ssh;
}

// ---------------- launch ----------------
extern "C" void kernel_launch(void* const* d_in, const int* in_sizes, int n_in,
                              void* d_out, int out_size) {
    (void)in_sizes; (void)n_in; (void)out_size;
    const float* q      = (const float*)d_in[0];
    const float* k      = (const float*)d_in[1];
    const float* v      = (const float*)d_in[2];
    const float* send   = (const float*)d_in[3];
    const float* recv   = (const float*)d_in[4];
    const float* ctrl   = (const float*)d_in[5];
    const float* h      = (const float*)d_in[6];
    const float* buffers= (const float*)d_in[7];
    const float* bond   = (const float*)d_in[8];
    const float* out_w  = (const float*)d_in[9];
    const float* out_b  = (const float*)d_in[10];
    const float* bq_w   = (const float*)d_in[11];
    const float* bq_b   = (const float*)d_in[12];
    const float* bk_w   = (const float*)d_in[13];
    const float* bk_b   = (const float*)d_in[14];
    const float* bv_w   = (const float*)d_in[15];
    const float* bv_b   = (const float*)d_in[16];
    const float* decay  = (const float*)d_in[17];

    float* out     = (float*)d_out;
    float* readout = out;                                   // [N,B,C]
    float* newbuf  = out + (size_t)Rr * Cc;                 // [N,B,T,C]
    float* attn    = newbuf + (size_t)Rr * Tt * Cc;         // [B,H,N,N]

    __nv_bfloat16 *p_msh, *p_msl, *p_wbh, *p_wbl, *p_hh, *p_hl;
    __nv_bfloat16 *p_owh, *p_owl, *p_bvh, *p_bvl, *p_w2h, *p_w2l;
    float *p_bqk, *p_s, *p_b2, *p_u;
    cudaGetSymbolAddress((void**)&p_msh, g_msh);
    cudaGetSymbolAddress((void**)&p_msl, g_msl);
    cudaGetSymbolAddress((void**)&p_wbh, g_wbh);
    cudaGetSymbolAddress((void**)&p_wbl, g_wbl);
    cudaGetSymbolAddress((void**)&p_hh,  g_hh);
    cudaGetSymbolAddress((void**)&p_hl,  g_hl);
    cudaGetSymbolAddress((void**)&p_owh, g_owt_h);
    cudaGetSymbolAddress((void**)&p_owl, g_owt_l);
    cudaGetSymbolAddress((void**)&p_bvh, g_bvt_h);
    cudaGetSymbolAddress((void**)&p_bvl, g_bvt_l);
    cudaGetSymbolAddress((void**)&p_w2h, g_w2t_h);
    cudaGetSymbolAddress((void**)&p_w2l, g_w2t_l);
    cudaGetSymbolAddress((void**)&p_bqk, g_bqk);
    cudaGetSymbolAddress((void**)&p_s,   g_s);
    cudaGetSymbolAddress((void**)&p_b2,  g_b2);
    cudaGetSymbolAddress((void**)&p_u,   g_u);

    const int attn_smem = 3 * 64 * 68 * sizeof(float);
    cudaFuncSetAttribute(attn_kernel, cudaFuncAttributeMaxDynamicSharedMemorySize, attn_smem);
    cudaFuncSetAttribute(gemm_mma<EpiMsgs>, cudaFuncAttributeMaxDynamicSharedMemorySize, GEMM_SMEM);
    cudaFuncSetAttribute(gemm_mma<EpiBias>, cudaFuncAttributeMaxDynamicSharedMemorySize, GEMM_SMEM);
    cudaFuncSetAttribute(gemm_mma<EpiRead>, cudaFuncAttributeMaxDynamicSharedMemorySize, GEMM_SMEM);

    // precomputes / independent work
    fold_w2<<<dim3(8, 4), 256>>>(bq_w, bk_w, p_w2h, p_w2l);
    fold_small<<<1, 256>>>(bq_w, bq_b, bk_w, bk_b, p_b2, p_u);
    split_h<<<(Rr * Mm) / 256, 256>>>(h, p_hh, p_hl);
    wsplit_t<<<dim3(8, 8), 256>>>(out_w, p_owh, p_owl);
    wsplit_t<<<dim3(8, 8), 256>>>(bv_w, p_bvh, p_bvl);
    shift_copy<<<4096, 256>>>((const float4*)buffers, (float4*)newbuf);
    attn_kernel<<<Bb * Hh, 256, attn_smem>>>(q, k, v, send, ctrl, bond, p_msh, p_msl, attn);

    {   EpiMsgs e{out_b, recv, newbuf};
        gemm_mma<EpiMsgs><<<dim3(128, 4), 256, GEMM_SMEM>>>(p_msh, p_msl, p_owh, p_owl, 256, e); }
    {   EpiBias e{p_bqk, p_b2};
        gemm_mma<EpiBias><<<dim3(128, 4), 256, GEMM_SMEM>>>(p_hh, p_hl, p_w2h, p_w2l, 128, e); }
    temporal_kernel<<<Rr, 256>>>(p_bqk, h, p_u, newbuf, decay, p_wbh, p_wbl, p_s);
    {   EpiRead e{readout, bv_b, p_s};
        gemm_mma<EpiRead><<<dim3(128, 4), 256, GEMM_SMEM>>>(p_wbh, p_wbl, p_bvh, p_bvl, 256, e); }
}

// round 6
// speedup vs baseline: 2.5044x; 1.3440x over previous
#include <cuda_runtime.h>
#include <cuda_bf16.h>
#include <cstdint>

#define Nn 64
#define Bb 256
#define Cc 256
#define Hh 4
#define HDd 64
#define Tt 8
#define Mm 128
#define Rr (Nn*Bb)   // 16384 rows

// ---------------- scratch (no allocations allowed) ----------------
__device__ __nv_bfloat16 g_msh[(size_t)Rr*Cc];   // msgs hi  [B*N, 256]
__device__ __nv_bfloat16 g_msl[(size_t)Rr*Cc];   // msgs lo
__device__ __nv_bfloat16 g_wbh[(size_t)Rr*Cc];   // wbuf hi  [N*B, 256]
__device__ __nv_bfloat16 g_wbl[(size_t)Rr*Cc];   // wbuf lo
__device__ __nv_bfloat16 g_hh [(size_t)Rr*Mm];   // h hi     [N*B, 128]
__device__ __nv_bfloat16 g_hl [(size_t)Rr*Mm];   // h lo
__device__ __nv_bfloat16 g_owt_h[(size_t)Cc*Cc]; // out_w^T hi  [n][k]
__device__ __nv_bfloat16 g_owt_l[(size_t)Cc*Cc];
__device__ __nv_bfloat16 g_bvt_h[(size_t)Cc*Cc]; // bv_w^T hi
__device__ __nv_bfloat16 g_bvt_l[(size_t)Cc*Cc];
__device__ __nv_bfloat16 g_w2t_h[(size_t)Cc*Mm]; // (bq_w@bk_w^T)^T hi [e][m]
__device__ __nv_bfloat16 g_w2t_l[(size_t)Cc*Mm];
__device__ float g_bqk [(size_t)Rr*Cc];          // [N*B, C]
__device__ float g_s   [(size_t)Rr];
__device__ float g_b2  [Cc];                     // bq_b @ bk_w^T
__device__ float g_u   [Mm + 1];                 // bq_w @ bk_b; [128]=bq_b.bk_b

// ================= helpers =================
__device__ __forceinline__ void bsplit(float x, __nv_bfloat16& hi, __nv_bfloat16& lo) {
    hi = __float2bfloat16(x);
    lo = __float2bfloat16(x - __bfloat162float(hi));
}
__device__ __forceinline__ uint32_t smem_u32(const void* p) {
    uint32_t a;
    asm("{ .reg .u64 t; cvta.to.shared.u64 t, %1; cvt.u32.u64 %0, t; }" : "=r"(a) : "l"(p));
    return a;
}
__device__ __forceinline__ void cp16(uint32_t d, const void* s) {
    asm volatile("cp.async.ca.shared.global [%0], [%1], 16;" :: "r"(d), "l"(s));
}
__device__ __forceinline__ void ldsm4(uint32_t* r, uint32_t a) {
    asm volatile("ldmatrix.sync.aligned.m8n8.x4.shared.b16 {%0,%1,%2,%3}, [%4];"
                 : "=r"(r[0]), "=r"(r[1]), "=r"(r[2]), "=r"(r[3]) : "r"(a));
}
__device__ __forceinline__ void mma16816(float* d, const uint32_t* a, const uint32_t* b) {
    asm volatile("mma.sync.aligned.m16n8k16.row.col.f32.bf16.bf16.f32 "
                 "{%0,%1,%2,%3}, {%4,%5,%6,%7}, {%8,%9}, {%0,%1,%2,%3};"
                 : "+f"(d[0]), "+f"(d[1]), "+f"(d[2]), "+f"(d[3])
                 : "r"(a[0]), "r"(a[1]), "r"(a[2]), "r"(a[3]), "r"(b[0]), "r"(b[1]));
}

// ============ weight folding ============
__global__ void fold_w2(const float* __restrict__ bq_w, const float* __restrict__ bk_w,
                        __nv_bfloat16* __restrict__ W2th, __nv_bfloat16* __restrict__ W2tl) {
    __shared__ float Aq[16*64];
    __shared__ float Bk[64*68];
    const int tid = threadIdx.x;
    const int m0 = blockIdx.x * 16;
    const int e0 = blockIdx.y * 64;
    const int e_l = tid & 63, grp = tid >> 6;
    float acc[4] = {0.f, 0.f, 0.f, 0.f};
    for (int c0 = 0; c0 < 256; c0 += 64) {
        {   int row = tid >> 4, col = (tid & 15) * 4;
            *(float4*)&Aq[row*64 + col] =
                *(const float4*)&bq_w[(size_t)(m0 + row) * 256 + c0 + col]; }
        #pragma unroll
        for (int i = 0; i < 4; i++) {
            int t = tid + i * 256;
            int row = t >> 4, col = (t & 15) * 4;
            *(float4*)&Bk[row*68 + col] =
                *(const float4*)&bk_w[(size_t)(e0 + row) * 256 + c0 + col];
        }
        __syncthreads();
        for (int c = 0; c < 64; c++) {
            float bv = Bk[e_l*68 + c];
            #pragma unroll
            for (int i = 0; i < 4; i++) acc[i] += Aq[(grp + 4*i)*64 + c] * bv;
        }
        __syncthreads();
    }
    #pragma unroll
    for (int i = 0; i < 4; i++) {
        __nv_bfloat16 hi, lo; bsplit(acc[i], hi, lo);
        size_t o = (size_t)(e0 + e_l) * Mm + (m0 + grp + 4*i);   // transposed [e][m]
        W2th[o] = hi; W2tl[o] = lo;
    }
}

__global__ void fold_small(const float* __restrict__ bq_w, const float* __restrict__ bq_b,
                           const float* __restrict__ bk_w, const float* __restrict__ bk_b,
                           float* __restrict__ b2, float* __restrict__ u) {
    int t = threadIdx.x;
    float s = 0.f;
    for (int c = 0; c < 256; c++) s += bq_b[c] * bk_w[(size_t)t * 256 + c];
    b2[t] = s;
    if (t < 128) {
        float s2 = 0.f;
        for (int c = 0; c < 256; c++) s2 += bq_w[(size_t)t * 256 + c] * bk_b[c];
        u[t] = s2;
    }
    if (t == 0) {
        float s3 = 0.f;
        for (int c = 0; c < 256; c++) s3 += bq_b[c] * bk_b[c];
        u[128] = s3;
    }
}

// split h [N*B,128] into bf16 hi/lo
__global__ void split_h(const float* __restrict__ h, __nv_bfloat16* __restrict__ hh,
                        __nv_bfloat16* __restrict__ hl) {
    size_t i = (size_t)blockIdx.x * blockDim.x + threadIdx.x;
    __nv_bfloat16 hi, lo; bsplit(h[i], hi, lo);
    hh[i] = hi; hl[i] = lo;
}

// transpose + split a 256x256 weight: out[n][k] = bf16split(W[k][n])
__global__ void wsplit_t(const float* __restrict__ W, __nv_bfloat16* __restrict__ th,
                         __nv_bfloat16* __restrict__ tl) {
    __shared__ float tile[32][33];
    const int bx = blockIdx.x, by = blockIdx.y;
    const int tx = threadIdx.x & 31, ty0 = threadIdx.x >> 5;
    #pragma unroll
    for (int i = 0; i < 4; i++) {
        int kk = by*32 + ty0 + i*8;
        tile[ty0 + i*8][tx] = W[(size_t)kk * 256 + bx*32 + tx];
    }
    __syncthreads();
    #pragma unroll
    for (int i = 0; i < 4; i++) {
        int n = bx*32 + ty0 + i*8;
        int kk = by*32 + tx;
        __nv_bfloat16 hi, lo; bsplit(tile[tx][ty0 + i*8], hi, lo);
        th[(size_t)n*256 + kk] = hi; tl[(size_t)n*256 + kk] = lo;
    }
}

// ============ fused graph attention per (b,h) ============
__device__ __forceinline__ unsigned okey(float v) {
    unsigned u = __float_as_uint(v);
    return (u & 0x80000000u) ? ~u : (u | 0x80000000u);
}

__global__ void attn_kernel(const float* __restrict__ q, const float* __restrict__ k,
                            const float* __restrict__ v, const float* __restrict__ sg,
                            const float* __restrict__ ctrl, const float* __restrict__ bond,
                            __nv_bfloat16* __restrict__ msh, __nv_bfloat16* __restrict__ msl,
                            float* __restrict__ attn_out) {
    extern __shared__ float sm[];
    float* QT = sm;               // [64 d][68]  Q^T, later A^T[m][n]
    float* KT = sm + 64*68;       // [64 d][68]  K^T, later Vs[m][d]
    float* Ls = sm + 2*64*68;     // [64 n][68]  logits

    const int bid = blockIdx.x;
    const int b = bid >> 2;
    const int hh = bid & 3;
    const int tid = threadIdx.x;

    #pragma unroll
    for (int i = 0; i < 4; i++) {
        int t = tid + i * 256;
        int row = t >> 4;
        int col = (t & 15) * 4;
        size_t g = ((size_t)row * Bb + b) * Cc + hh * HDd + col;
        float4 qv = *(const float4*)&q[g];
        float4 kv = *(const float4*)&k[g];
        QT[(col+0)*68 + row] = qv.x; QT[(col+1)*68 + row] = qv.y;
        QT[(col+2)*68 + row] = qv.z; QT[(col+3)*68 + row] = qv.w;
        KT[(col+0)*68 + row] = kv.x; KT[(col+1)*68 + row] = kv.y;
        KT[(col+2)*68 + row] = kv.z; KT[(col+3)*68 + row] = kv.w;
    }
    __syncthreads();

    const int n0 = (tid >> 4) * 4;
    const int m0 = (tid & 15) * 4;

    float acc[4][4];
    #pragma unroll
    for (int i = 0; i < 4; i++)
        #pragma unroll
        for (int j = 0; j < 4; j++) acc[i][j] = 0.f;
    for (int d = 0; d < 64; d++) {
        float4 a  = *(float4*)&QT[d*68 + n0];
        float4 bv = *(float4*)&KT[d*68 + m0];
        float av[4] = {a.x, a.y, a.z, a.w};
        float bw[4] = {bv.x, bv.y, bv.z, bv.w};
        #pragma unroll
        for (int i = 0; i < 4; i++)
            #pragma unroll
            for (int j = 0; j < 4; j++) acc[i][j] += av[i] * bw[j];
    }
    float cb[4];
    #pragma unroll
    for (int j = 0; j < 4; j++)
        cb[j] = ctrl[((size_t)(m0 + j) * Bb + b) * Hh + hh];
    #pragma unroll
    for (int i = 0; i < 4; i++) {
        int n = n0 + i;
        float4 bd = *(const float4*)&bond[(size_t)n * Nn + m0];
        float vals[4];
        vals[0] = acc[i][0]*0.125f + bd.x + cb[0];
        vals[1] = acc[i][1]*0.125f + bd.y + cb[1];
        vals[2] = acc[i][2]*0.125f + bd.z + cb[2];
        vals[3] = acc[i][3]*0.125f + bd.w + cb[3];
        int dsel = n - m0;
        if (dsel >= 0 && dsel < 4) vals[dsel] = -1e30f;
        *(float4*)&Ls[n*68 + m0] = *(float4*)vals;
    }
    __syncthreads();

    // load gated V into KT (row-major Vs[m][d])
    #pragma unroll
    for (int i = 0; i < 4; i++) {
        int t = tid + i * 256;
        int row = t >> 4;
        int col = (t & 15) * 4;
        size_t g = ((size_t)row * Bb + b) * Cc + hh * HDd + col;
        float4 vv = *(const float4*)&v[g];
        float4 gg = *(const float4*)&sg[g];
        vv.x *= gg.x; vv.y *= gg.y; vv.z *= gg.z; vv.w *= gg.w;
        *(float4*)&KT[row*68 + col] = vv;
    }

    // warp-parallel exact top-8 (REDUX + ballot, lowest-index tie-break) + softmax
    const int w = tid >> 5, lane = tid & 31;
    const size_t ao_base = (((size_t)b * Hh + hh) * Nn) * Nn;
    for (int rr = 0; rr < 8; rr++) {
        int row = w * 8 + rr;
        float v0 = Ls[row*68 + lane];
        float v1 = Ls[row*68 + lane + 32];
        unsigned k0 = okey(v0), k1 = okey(v1);
        bool s0 = false, s1 = false;
        float mx = 0.f;
        #pragma unroll
        for (int it = 0; it < 8; it++) {
            unsigned c0 = s0 ? 0u : k0;
            unsigned c1 = s1 ? 0u : k1;
            unsigned m = c0 > c1 ? c0 : c1;
            unsigned best = __reduce_max_sync(0xffffffffu, m);
            if (it == 0)
                mx = __uint_as_float((best & 0x80000000u) ? (best & 0x7fffffffu) : ~best);
            unsigned b0 = __ballot_sync(0xffffffffu, c0 == best);
            if (b0) {
                if (lane == __ffs(b0) - 1) s0 = true;
            } else {
                unsigned b1 = __ballot_sync(0xffffffffu, c1 == best);
                if (lane == __ffs(b1) - 1) s1 = true;
            }
        }
        float e0 = s0 ? __expf(v0 - mx) : 0.f;
        float e1 = s1 ? __expf(v1 - mx) : 0.f;
        float ssum = e0 + e1;
        #pragma unroll
        for (int o = 16; o > 0; o >>= 1) ssum += __shfl_xor_sync(0xffffffffu, ssum, o);
        float inv = 1.f / ssum;
        e0 *= inv; e1 *= inv;
        attn_out[ao_base + (size_t)row * Nn + lane]      = e0;
        attn_out[ao_base + (size_t)row * Nn + lane + 32] = e1;
        QT[lane*68 + row]      = e0;    // A^T[m][n]
        QT[(lane+32)*68 + row] = e1;
    }
    __syncthreads();

    // msgs = attn @ Vg; write bf16 hi/lo splits
    float acc2[4][4];
    #pragma unroll
    for (int i = 0; i < 4; i++)
        #pragma unroll
        for (int j = 0; j < 4; j++) acc2[i][j] = 0.f;
    const int d0 = m0;
    for (int m = 0; m < 64; m++) {
        float4 a  = *(float4*)&QT[m*68 + n0];
        float4 vv = *(float4*)&KT[m*68 + d0];
        float av[4] = {a.x, a.y, a.z, a.w};
        float vw[4] = {vv.x, vv.y, vv.z, vv.w};
        #pragma unroll
        for (int i = 0; i < 4; i++)
            #pragma unroll
            for (int j = 0; j < 4; j++) acc2[i][j] += av[i] * vw[j];
    }
    #pragma unroll
    for (int i = 0; i < 4; i++) {
        size_t o = ((size_t)b * Nn + n0 + i) * Cc + hh * HDd + d0;
        __nv_bfloat16 hi[4], lo[4];
        #pragma unroll
        for (int j = 0; j < 4; j++) bsplit(acc2[i][j], hi[j], lo[j]);
        __nv_bfloat162 h01, h23, l01, l23;
        h01.x = hi[0]; h01.y = hi[1]; h23.x = hi[2]; h23.y = hi[3];
        l01.x = lo[0]; l01.y = lo[1]; l23.x = lo[2]; l23.y = lo[3];
        *(__nv_bfloat162*)&msh[o]     = h01;
        *(__nv_bfloat162*)&msh[o + 2] = h23;
        *(__nv_bfloat162*)&msl[o]     = l01;
        *(__nv_bfloat162*)&msl[o + 2] = l23;
    }
}

// ============ split-bf16 HMMA GEMM: [16384 x K] @ [K x 256] ============
struct EpiMsgs {   // (acc + out_b[c]) * recv -> newbuf slot T-1
    const float* out_b; const float* recv; float* nb;
    __device__ __forceinline__ void store(int r, int c, float acc) const {
        int n = r & 63, b = r >> 6;
        size_t rb = (size_t)n * Bb + b;
        float val = (acc + out_b[c]) * recv[rb * Cc + c];
        nb[(rb * Tt + (Tt - 1)) * Cc + c] = val;
    }
};
struct EpiBias {
    float* out; const float* bias;
    __device__ __forceinline__ void store(int r, int c, float acc) const {
        out[(size_t)r * Cc + c] = acc + bias[c];
    }
};
struct EpiRead {
    float* out; const float* bias; const float* s;
    __device__ __forceinline__ void store(int r, int c, float acc) const {
        out[(size_t)r * Cc + c] = acc + s[r] * bias[c];
    }
};

// smem: A [2 buf][2 split][128 rows][40 bf16]  = 40960 B
//       B [2 buf][2 split][ 64 rows][40 bf16]  = 20480 B
#define GEMM_SMEM (40960 + 20480)

template<typename Epi>
__global__ void __launch_bounds__(256, 2)
gemm_mma(const __nv_bfloat16* __restrict__ Ah, const __nv_bfloat16* __restrict__ Al,
         const __nv_bfloat16* __restrict__ Bth, const __nv_bfloat16* __restrict__ Btl,
         int K, Epi epi) {
    extern __shared__ char smem[];
    const uint32_t sbA = smem_u32(smem);
    const uint32_t sbB = sbA + 40960;
    const int tid = threadIdx.x, wid = tid >> 5, lane = tid & 31;
    const int r0 = blockIdx.x * 128, c0 = blockIdx.y * 64;
    const int wm = (wid & 3) * 32, wn = (wid >> 2) * 32;
    const int NS = K >> 5;            // 32-wide K stages

    float acc[2][4][4];
    #pragma unroll
    for (int mt = 0; mt < 2; mt++)
        #pragma unroll
        for (int nt = 0; nt < 4; nt++)
            #pragma unroll
            for (int j = 0; j < 4; j++) acc[mt][nt][j] = 0.f;

    auto loadChunk = [&](int stage, int buf) {
        const char* srcAh = (const char*)(Ah + (size_t)r0 * K + stage * 32);
        const char* srcAl = (const char*)(Al + (size_t)r0 * K + stage * 32);
        #pragma unroll
        for (int i = 0; i < 4; i++) {
            int ch = tid + i * 256;              // 0..1023
            int s = ch >> 9;
            int rem = ch & 511;
            int row = rem >> 2, seg = rem & 3;
            uint32_t dst = sbA + (uint32_t)(((buf*2 + s)*128 + row) * 80 + seg * 16);
            const char* src = (s ? srcAl : srcAh) + (size_t)row * (K * 2) + seg * 16;
            cp16(dst, src);
        }
        const char* srcBh = (const char*)(Bth + (size_t)c0 * K + stage * 32);
        const char* srcBl = (const char*)(Btl + (size_t)c0 * K + stage * 32);
        #pragma unroll
        for (int i = 0; i < 2; i++) {
            int ch = tid + i * 256;              // 0..511
            int s = ch >> 8;
            int rem = ch & 255;
            int row = rem >> 2, seg = rem & 3;
            uint32_t dst = sbB + (uint32_t)(((buf*2 + s)*64 + row) * 80 + seg * 16);
            const char* src = (s ? srcBl : srcBh) + (size_t)row * (K * 2) + seg * 16;
            cp16(dst, src);
        }
        asm volatile("cp.async.commit_group;");
    };

    loadChunk(0, 0);

    const int lg = lane >> 3, lr = lane & 7;

    for (int i = 0; i < NS; i++) {
        if (i + 1 < NS) {
            loadChunk(i + 1, (i + 1) & 1);
            asm volatile("cp.async.wait_group 1;");
        } else {
            asm volatile("cp.async.wait_group 0;");
        }
        __syncthreads();
        int buf = i & 1;
        #pragma unroll
        for (int kk = 0; kk < 2; kk++) {
            uint32_t Af[2][2][4];   // [split][mtile][4]
            uint32_t Bf[2][4][2];   // [split][ntile][2]
            #pragma unroll
            for (int s = 0; s < 2; s++)
                #pragma unroll
                for (int mt = 0; mt < 2; mt++) {
                    int row = wm + mt*16 + (lg & 1)*8 + lr;
                    int kc  = kk*16 + (lg >> 1)*8;
                    ldsm4(Af[s][mt], sbA + (uint32_t)(((buf*2 + s)*128 + row)*80 + kc*2));
                }
            #pragma unroll
            for (int s = 0; s < 2; s++)
                #pragma unroll
                for (int nt2 = 0; nt2 < 2; nt2++) {
                    int row = wn + nt2*16 + (lg >> 1)*8 + lr;
                    int kc  = kk*16 + (lg & 1)*8;
                    uint32_t r[4];
                    ldsm4(r, sbB + (uint32_t)(((buf*2 + s)*64 + row)*80 + kc*2));
                    Bf[s][nt2*2][0]   = r[0]; Bf[s][nt2*2][1]   = r[1];
                    Bf[s][nt2*2+1][0] = r[2]; Bf[s][nt2*2+1][1] = r[3];
                }
            #pragma unroll
            for (int mt = 0; mt < 2; mt++)
                #pragma unroll
                for (int nt = 0; nt < 4; nt++) {
                    mma16816(acc[mt][nt], Af[0][mt], Bf[0][nt]);
                    mma16816(acc[mt][nt], Af[0][mt], Bf[1][nt]);
                    mma16816(acc[mt][nt], Af[1][mt], Bf[0][nt]);
                }
        }
        __syncthreads();
    }

    const int g = lane >> 2, tg = lane & 3;
    #pragma unroll
    for (int mt = 0; mt < 2; mt++)
        #pragma unroll
        for (int nt = 0; nt < 4; nt++) {
            int row = r0 + wm + mt*16 + g;
            int col = c0 + wn + nt*8 + tg*2;
            epi.store(row,     col,     acc[mt][nt][0]);
            epi.store(row,     col + 1, acc[mt][nt][1]);
            epi.store(row + 8, col,     acc[mt][nt][2]);
            epi.store(row + 8, col + 1, acc[mt][nt][3]);
        }
}

// ---------------- temporal: fused buffer-shift + ba softmax + weighted sum ----------------
// reads buffers slots 1..7 + newbuf slot 7 (msgs, from EpiMsgs);
// writes newbuf slots 0..6 (the shift), wbuf hi/lo splits, s.
__global__ void temporal_kernel(const float* __restrict__ bqk,
                                const float* __restrict__ h,
                                const float* __restrict__ u,
                                const float* __restrict__ buffers,
                                float* __restrict__ newbuf,
                                const float* __restrict__ decay_logit,
                                __nv_bfloat16* __restrict__ wbh,
                                __nv_bfloat16* __restrict__ wbl,
                                float* __restrict__ svec) {
    const int r = blockIdx.x;            // r = n*B + b
    const int c = threadIdx.x;           // 0..255
    const float* ob = buffers + (size_t)r * (Tt * Cc);
    float* nb = newbuf + (size_t)r * (Tt * Cc);

    float qk = bqk[(size_t)r * Cc + c];
    float nbv[8];
    float p[9];
    #pragma unroll
    for (int t = 0; t < 7; t++) nbv[t] = ob[(t + 1) * Cc + c];
    nbv[7] = nb[7 * Cc + c];
    #pragma unroll
    for (int t = 0; t < 8; t++) p[t] = qk * nbv[t];
    p[8] = (c < Mm) ? h[(size_t)r * Mm + c] * u[c] : 0.f;

    // fused shift: write slots 0..6
    #pragma unroll
    for (int t = 0; t < 7; t++) nb[t * Cc + c] = nbv[t];

    #pragma unroll
    for (int t = 0; t < 9; t++)
        #pragma unroll
        for (int o = 16; o > 0; o >>= 1)
            p[t] += __shfl_xor_sync(0xffffffffu, p[t], o);

    __shared__ float red[8][9];
    __shared__ float wsh[8];
    __shared__ float ssh;
    int warp = c >> 5, lane = c & 31;
    if (lane == 0) {
        #pragma unroll
        for (int t = 0; t < 9; t++) red[warp][t] = p[t];
    }
    __syncthreads();
    if (c == 0) {
        float bqb = u[128];
        #pragma unroll
        for (int w = 0; w < 8; w++) bqb += red[w][8];
        float ba[8]; float mx = -3e38f;
        #pragma unroll
        for (int t = 0; t < 8; t++) {
            float s = 0.f;
            #pragma unroll
            for (int w = 0; w < 8; w++) s += red[w][t];
            ba[t] = (s + bqb) * 0.0625f;
            mx = fmaxf(mx, ba[t]);
        }
        float sum = 0.f;
        #pragma unroll
        for (int t = 0; t < 8; t++) { ba[t] = __expf(ba[t] - mx); sum += ba[t]; }
        float inv = 1.f / sum;
        float dec = 1.f / (1.f + __expf(-decay_logit[0]));
        float powv = dec, s2 = 0.f;
        float wv[8];
        for (int t = 7; t >= 0; t--) {
            wv[t] = ba[t] * inv * powv;
            powv *= dec;
            s2 += wv[t];
        }
        #pragma unroll
        for (int t = 0; t < 8; t++) wsh[t] = wv[t];
        ssh = s2;
    }
    __syncthreads();
    float acc = 0.f;
    #pragma unroll
    for (int t = 0; t < 8; t++) acc += wsh[t] * nbv[t];
    __nv_bfloat16 hi, lo; bsplit(acc, hi, lo);
    wbh[(size_t)r * Cc + c] = hi;
    wbl[(size_t)r * Cc + c] = lo;
    if (c == 0) svec[r] = ssh;
}

// ---------------- launch ----------------
struct LaunchCtx {
    cudaStream_t s1, s2;
    cudaEvent_t eF, e1, e2;
    LaunchCtx() {
        cudaStreamCreate(&s1);
        cudaStreamCreate(&s2);
        cudaEventCreateWithFlags(&eF, cudaEventDisableTiming);
        cudaEventCreateWithFlags(&e1, cudaEventDisableTiming);
        cudaEventCreateWithFlags(&e2, cudaEventDisableTiming);
    }
};

extern "C" void kernel_launch(void* const* d_in, const int* in_sizes, int n_in,
                              void* d_out, int out_size) {
    (void)in_sizes; (void)n_in; (void)out_size;
    const float* q      = (const float*)d_in[0];
    const float* k      = (const float*)d_in[1];
    const float* v      = (const float*)d_in[2];
    const float* send   = (const float*)d_in[3];
    const float* recv   = (const float*)d_in[4];
    const float* ctrl   = (const float*)d_in[5];
    const float* h      = (const float*)d_in[6];
    const float* buffers= (const float*)d_in[7];
    const float* bond   = (const float*)d_in[8];
    const float* out_w  = (const float*)d_in[9];
    const float* out_b  = (const float*)d_in[10];
    const float* bq_w   = (const float*)d_in[11];
    const float* bq_b   = (const float*)d_in[12];
    const float* bk_w   = (const float*)d_in[13];
    const float* bk_b   = (const float*)d_in[14];
    const float* bv_w   = (const float*)d_in[15];
    const float* bv_b   = (const float*)d_in[16];
    const float* decay  = (const float*)d_in[17];

    float* out     = (float*)d_out;
    float* readout = out;                                   // [N,B,C]
    float* newbuf  = out + (size_t)Rr * Cc;                 // [N,B,T,C]
    float* attn    = newbuf + (size_t)Rr * Tt * Cc;         // [B,H,N,N]

    __nv_bfloat16 *p_msh, *p_msl, *p_wbh, *p_wbl, *p_hh, *p_hl;
    __nv_bfloat16 *p_owh, *p_owl, *p_bvh, *p_bvl, *p_w2h, *p_w2l;
    float *p_bqk, *p_s, *p_b2, *p_u;
    cudaGetSymbolAddress((void**)&p_msh, g_msh);
    cudaGetSymbolAddress((void**)&p_msl, g_msl);
    cudaGetSymbolAddress((void**)&p_wbh, g_wbh);
    cudaGetSymbolAddress((void**)&p_wbl, g_wbl);
    cudaGetSymbolAddress((void**)&p_hh,  g_hh);
    cudaGetSymbolAddress((void**)&p_hl,  g_hl);
    cudaGetSymbolAddress((void**)&p_owh, g_owt_h);
    cudaGetSymbolAddress((void**)&p_owl, g_owt_l);
    cudaGetSymbolAddress((void**)&p_bvh, g_bvt_h);
    cudaGetSymbolAddress((void**)&p_bvl, g_bvt_l);
    cudaGetSymbolAddress((void**)&p_w2h, g_w2t_h);
    cudaGetSymbolAddress((void**)&p_w2l, g_w2t_l);
    cudaGetSymbolAddress((void**)&p_bqk, g_bqk);
    cudaGetSymbolAddress((void**)&p_s,   g_s);
    cudaGetSymbolAddress((void**)&p_b2,  g_b2);
    cudaGetSymbolAddress((void**)&p_u,   g_u);

    const int attn_smem = 3 * 64 * 68 * sizeof(float);
    cudaFuncSetAttribute(attn_kernel, cudaFuncAttributeMaxDynamicSharedMemorySize, attn_smem);
    cudaFuncSetAttribute(gemm_mma<EpiMsgs>, cudaFuncAttributeMaxDynamicSharedMemorySize, GEMM_SMEM);
    cudaFuncSetAttribute(gemm_mma<EpiBias>, cudaFuncAttributeMaxDynamicSharedMemorySize, GEMM_SMEM);
    cudaFuncSetAttribute(gemm_mma<EpiRead>, cudaFuncAttributeMaxDynamicSharedMemorySize, GEMM_SMEM);

    // streams/events created on first (non-captured) correctness call
    static LaunchCtx ctx;

    // fork side streams off the capture/default stream
    cudaEventRecord(ctx.eF, 0);
    cudaStreamWaitEvent(ctx.s1, ctx.eF, 0);
    cudaStreamWaitEvent(ctx.s2, ctx.eF, 0);

    // main stream: the longest independent pole
    attn_kernel<<<Bb * Hh, 256, attn_smem>>>(q, k, v, send, ctrl, bond, p_msh, p_msl, attn);

    // s1: weight transposes/splits for the two big GEMMs
    wsplit_t<<<dim3(8, 8), 256, 0, ctx.s1>>>(out_w, p_owh, p_owl);
    wsplit_t<<<dim3(8, 8), 256, 0, ctx.s1>>>(bv_w, p_bvh, p_bvl);
    cudaEventRecord(ctx.e1, ctx.s1);

    // s2: bq/bk fold chain + bqk GEMM (independent of attn)
    fold_w2<<<dim3(8, 4), 256, 0, ctx.s2>>>(bq_w, bk_w, p_w2h, p_w2l);
    split_h<<<(Rr * Mm) / 256, 256, 0, ctx.s2>>>(h, p_hh, p_hl);
    fold_small<<<1, 256, 0, ctx.s2>>>(bq_w, bq_b, bk_w, bk_b, p_b2, p_u);
    {   EpiBias e{p_bqk, p_b2};
        gemm_mma<EpiBias><<<dim3(128, 4), 256, GEMM_SMEM, ctx.s2>>>(p_hh, p_hl, p_w2h, p_w2l, 128, e); }
    cudaEventRecord(ctx.e2, ctx.s2);

    // join: msgs GEMM needs attn (main) + out_w split (s1)
    cudaStreamWaitEvent(0, ctx.e1, 0);
    {   EpiMsgs e{out_b, recv, newbuf};
        gemm_mma<EpiMsgs><<<dim3(128, 4), 256, GEMM_SMEM>>>(p_msh, p_msl, p_owh, p_owl, 256, e); }

    // temporal needs bqk (s2) + newbuf slot7 (main) + buffers
    cudaStreamWaitEvent(0, ctx.e2, 0);
    temporal_kernel<<<Rr, 256>>>(p_bqk, h, p_u, buffers, newbuf, decay, p_wbh, p_wbl, p_s);

    {   EpiRead e{readout, bv_b, p_s};
        gemm_mma<EpiRead><<<dim3(128, 4), 256, GEMM_SMEM>>>(p_wbh, p_wbl, p_bvh, p_bvl, 256, e); }
}